// round 14
// baseline (speedup 1.0000x reference)
// Round 14: identical resubmission of round 13 (container failure was infra;
// the gather-MLP4 candidate never executed).
// Gather inner loop unrolled x4 with 4 independent accumulators
// (MLP 4 on the csrsrc->h pointer chase). Rest unchanged from 549µs config.
#include <cuda_runtime.h>
#include <stdint.h>

#define NN 50000
#define NE 800000
#define NG 64
#define IND 512
#define HIDD 256
#define OUTD 256
#define EPSV 0.1f

typedef unsigned int u32;

__device__ __forceinline__ int clampi(int v, int lo, int hi) {
    return v < lo ? lo : (v > hi ? hi : v);
}

// ---------------- scratch (device globals) ----------------
__device__ __align__(16) int   g_degi[NN];
__device__ __align__(16) int   g_rowstart[NN];
__device__ __align__(16) int   g_fill[NN];
__device__ __align__(16) int   g_bsum[64];
__device__ __align__(16) int   g_boff[64];
__device__ __align__(16) int   g_csrsrc[NE];
__device__ __align__(16) int   g_perm[NE];
__device__ __align__(16) float g_dinv[NN];
__device__ __align__(16) float g_norm[NE];
__device__ __align__(16) float g_coef[NE];
__device__ __align__(16) float g_al[NN];
__device__ __align__(16) float g_ar[NN];
__device__ __align__(16) float g_h[(size_t)NN * HIDD];
__device__ __align__(16) float g_h0[(size_t)NN * HIDD];
__device__ __align__(16) float g_agg[(size_t)NN * HIDD];
__device__ __align__(16) float g_sums[NG * OUTD];
__device__ __align__(16) float g_cnt[NG];

// ---------------- setup kernels ----------------
__global__ void zeroi_kernel() {
    int i = blockIdx.x * blockDim.x + threadIdx.x;
    if (i < NN) { g_degi[i] = 0; g_fill[i] = 0; }
    if (i < NG * OUTD) g_sums[i] = 0.f;
    if (i < NG) g_cnt[i] = 0.f;
}

__global__ void deg_kernel(const int* __restrict__ ei) {
    int e = blockIdx.x * blockDim.x + threadIdx.x;
    if (e < NE) {
        int d = clampi(ei[NE + e], 0, NN - 1);
        atomicAdd(&g_degi[d], 1);
    }
}

__global__ void dinv_kernel() {
    int i = blockIdx.x * blockDim.x + threadIdx.x;
    if (i < NN) {
        float d = (float)g_degi[i];
        g_dinv[i] = (d > 0.f) ? rsqrtf(fmaxf(d, 1.f)) : 0.f;
    }
}

// 3-phase scan
__global__ void scanA_kernel() {
    int tid = threadIdx.x;
    int i = blockIdx.x * 1024 + tid;
    int lane = tid & 31, w = tid >> 5;
    int v = (i < NN) ? g_degi[i] : 0;
    int incl = v;
#pragma unroll
    for (int o = 1; o < 32; o <<= 1) {
        int t = __shfl_up_sync(0xFFFFFFFFu, incl, o);
        if (lane >= o) incl += t;
    }
    __shared__ int wsum[32];
    if (lane == 31) wsum[w] = incl;
    __syncthreads();
    if (w == 0) {
        int x = wsum[lane];
        int xi = x;
#pragma unroll
        for (int o = 1; o < 32; o <<= 1) {
            int t = __shfl_up_sync(0xFFFFFFFFu, xi, o);
            if (lane >= o) xi += t;
        }
        wsum[lane] = xi;
    }
    __syncthreads();
    int woff = (w > 0) ? wsum[w - 1] : 0;
    if (i < NN) g_rowstart[i] = woff + incl - v;
    if (tid == 1023) g_bsum[blockIdx.x] = wsum[31];
}

__global__ void scanB_kernel(int nblocks) {
    int tid = threadIdx.x;
    int lane = tid & 31, w = tid >> 5;
    int v = (tid < nblocks) ? g_bsum[tid] : 0;
    int incl = v;
#pragma unroll
    for (int o = 1; o < 32; o <<= 1) {
        int t = __shfl_up_sync(0xFFFFFFFFu, incl, o);
        if (lane >= o) incl += t;
    }
    __shared__ int ws[2];
    if (lane == 31) ws[w] = incl;
    __syncthreads();
    int off = (w == 1) ? ws[0] : 0;
    if (tid < nblocks) g_boff[tid] = off + incl - v;
}

__global__ void scanC_kernel() {
    int i = blockIdx.x * 1024 + threadIdx.x;
    if (i < NN) g_rowstart[i] += g_boff[blockIdx.x];
}

__global__ void fill_kernel(const int* __restrict__ ei) {
    int e = blockIdx.x * blockDim.x + threadIdx.x;
    if (e < NE) {
        int s = clampi(ei[e], 0, NN - 1);
        int d = clampi(ei[NE + e], 0, NN - 1);
        int pos = g_rowstart[d] + atomicAdd(&g_fill[d], 1);
        pos = clampi(pos, 0, NE - 1);
        g_csrsrc[pos] = s;
        g_perm[e] = pos;
        g_norm[e] = g_dinv[s] * g_dinv[d];
    }
}

// ---------------- per-layer kernels ----------------
__global__ void attn_kernel(int sel,
                            const float* __restrict__ alw, const float* __restrict__ alb,
                            const float* __restrict__ arw, const float* __restrict__ arb,
                            int layer) {
    int node = (blockIdx.x * blockDim.x + threadIdx.x) >> 5;
    int lane = threadIdx.x & 31;
    if (node >= NN) return;
    const float* h = sel ? g_agg : g_h;
    const float* hp = h + (size_t)node * HIDD;
    const float* wl = alw + layer * HIDD;
    const float* wr = arw + layer * HIDD;
    float sl = 0.f, sr = 0.f;
#pragma unroll
    for (int i = 0; i < 8; i++) {
        float v = hp[lane + 32 * i];
        sl = fmaf(v, wl[lane + 32 * i], sl);
        sr = fmaf(v, wr[lane + 32 * i], sr);
    }
#pragma unroll
    for (int o = 16; o; o >>= 1) {
        sl += __shfl_xor_sync(0xFFFFFFFFu, sl, o);
        sr += __shfl_xor_sync(0xFFFFFFFFu, sr, o);
    }
    if (lane == 0) {
        g_al[node] = sl + alb[layer];
        g_ar[node] = sr + arb[layer];
    }
}

__global__ void coef_kernel(const int* __restrict__ ei) {
    int e = blockIdx.x * blockDim.x + threadIdx.x;
    if (e < NE) {
        int s = clampi(ei[e], 0, NN - 1);
        int d = clampi(ei[NE + e], 0, NN - 1);
        g_coef[g_perm[e]] = g_norm[e] * tanhf(g_al[s] + g_ar[d]);
    }
}

// gather with x4 unroll: 4 independent accumulators -> MLP 4 on the chase.
__global__ __launch_bounds__(256) void gather_kernel(int sel, int do_relu)
{
    int node = blockIdx.x * 4 + (threadIdx.x >> 6);
    int c = threadIdx.x & 63;
    if (node >= NN) return;
    const float* h = sel ? g_agg : g_h;
    float* outp    = sel ? g_h   : g_agg;
    const int* __restrict__ src = g_csrsrc;
    const float* __restrict__ cf = g_coef;
    int beg = g_rowstart[node];
    int n = g_degi[node];

    float4 a0 = ((const float4*)(g_h0 + (size_t)node * HIDD))[c];
    a0.x *= EPSV; a0.y *= EPSV; a0.z *= EPSV; a0.w *= EPSV;
    float4 a1 = make_float4(0.f, 0.f, 0.f, 0.f);
    float4 a2 = make_float4(0.f, 0.f, 0.f, 0.f);
    float4 a3 = make_float4(0.f, 0.f, 0.f, 0.f);

    int i = 0;
    for (; i + 4 <= n; i += 4) {
        int s0 = __ldg(&src[beg + i]);
        int s1 = __ldg(&src[beg + i + 1]);
        int s2 = __ldg(&src[beg + i + 2]);
        int s3 = __ldg(&src[beg + i + 3]);
        float c0 = __ldg(&cf[beg + i]);
        float c1 = __ldg(&cf[beg + i + 1]);
        float c2 = __ldg(&cf[beg + i + 2]);
        float c3 = __ldg(&cf[beg + i + 3]);
        float4 v0 = __ldg((const float4*)(h + (size_t)s0 * HIDD) + c);
        float4 v1 = __ldg((const float4*)(h + (size_t)s1 * HIDD) + c);
        float4 v2 = __ldg((const float4*)(h + (size_t)s2 * HIDD) + c);
        float4 v3 = __ldg((const float4*)(h + (size_t)s3 * HIDD) + c);
        a0.x = fmaf(c0, v0.x, a0.x); a0.y = fmaf(c0, v0.y, a0.y);
        a0.z = fmaf(c0, v0.z, a0.z); a0.w = fmaf(c0, v0.w, a0.w);
        a1.x = fmaf(c1, v1.x, a1.x); a1.y = fmaf(c1, v1.y, a1.y);
        a1.z = fmaf(c1, v1.z, a1.z); a1.w = fmaf(c1, v1.w, a1.w);
        a2.x = fmaf(c2, v2.x, a2.x); a2.y = fmaf(c2, v2.y, a2.y);
        a2.z = fmaf(c2, v2.z, a2.z); a2.w = fmaf(c2, v2.w, a2.w);
        a3.x = fmaf(c3, v3.x, a3.x); a3.y = fmaf(c3, v3.y, a3.y);
        a3.z = fmaf(c3, v3.z, a3.z); a3.w = fmaf(c3, v3.w, a3.w);
    }
    for (; i < n; i++) {
        int s = __ldg(&src[beg + i]);
        float cc = __ldg(&cf[beg + i]);
        float4 v = __ldg((const float4*)(h + (size_t)s * HIDD) + c);
        a0.x = fmaf(cc, v.x, a0.x); a0.y = fmaf(cc, v.y, a0.y);
        a0.z = fmaf(cc, v.z, a0.z); a0.w = fmaf(cc, v.w, a0.w);
    }
    float4 acc;
    acc.x = (a0.x + a1.x) + (a2.x + a3.x);
    acc.y = (a0.y + a1.y) + (a2.y + a3.y);
    acc.z = (a0.z + a1.z) + (a2.z + a3.z);
    acc.w = (a0.w + a1.w) + (a2.w + a3.w);
    if (do_relu) {
        acc.x = fmaxf(acc.x, 0.f); acc.y = fmaxf(acc.y, 0.f);
        acc.z = fmaxf(acc.z, 0.f); acc.w = fmaxf(acc.w, 0.f);
    }
    ((float4*)(outp + (size_t)node * HIDD))[c] = acc;
}

// ---------------- bf16 3-term tensor-core GEMM ----------------
__device__ __forceinline__ u32 cvt_bf2(float lo, float hi) {
    u32 d;
    asm("cvt.rn.bf16x2.f32 %0, %1, %2;" : "=r"(d) : "f"(hi), "f"(lo));
    return d;
}
__device__ __forceinline__ void split2(float lo, float hi, u32& big, u32& sml) {
    big = cvt_bf2(lo, hi);
    float blo = __uint_as_float(big << 16);
    float bhi = __uint_as_float(big & 0xFFFF0000u);
    sml = cvt_bf2(lo - blo, hi - bhi);
}
__device__ __forceinline__ void mma_bf16(float* c, const u32* a, const u32* b) {
    asm volatile(
        "mma.sync.aligned.m16n8k16.row.col.f32.bf16.bf16.f32 "
        "{%0,%1,%2,%3}, {%4,%5,%6,%7}, {%8,%9}, {%0,%1,%2,%3};"
        : "+f"(c[0]), "+f"(c[1]), "+f"(c[2]), "+f"(c[3])
        : "r"(a[0]), "r"(a[1]), "r"(a[2]), "r"(a[3]), "r"(b[0]), "r"(b[1]));
}

template <int CFG>
__global__ __launch_bounds__(256) void bfgemm_kernel(
    const float* __restrict__ Aext, const float* __restrict__ B,
    const float* __restrict__ bias, float* __restrict__ Cext,
    int M, int K, int N)
{
    const float* A = (CFG == 0) ? Aext : (const float*)g_h;
    float* C       = (CFG == 0) ? (float*)g_h : Cext;

    __shared__ u32 Abig[128][20], Asml[128][20];
    __shared__ u32 Bbig[8][72],  Bsml[8][72];

    const int tid  = threadIdx.x;
    const int lane = tid & 31;
    const int warp = tid >> 5;
    const int wm = warp >> 1;
    const int wn = warp & 1;
    const int g   = lane >> 2;
    const int tig = lane & 3;
    const int row0 = blockIdx.x * 128;
    const int col0 = blockIdx.y * 64;
    const int rw = wm * 32;
    const int cw = wn * 32;

    float acc[2][4][4];
#pragma unroll
    for (int mt = 0; mt < 2; mt++)
#pragma unroll
        for (int nt = 0; nt < 4; nt++)
#pragma unroll
            for (int r = 0; r < 4; r++) acc[mt][nt][r] = 0.f;

    const int r_a  = tid >> 2;
    const int kq_a = tid & 3;
    const bool va0 = (row0 + r_a) < M;
    const bool va1 = (row0 + r_a + 64) < M;
    const int p_b  = tid >> 4;
    const int nq_b = tid & 15;

    const int KT = K >> 4;
    float4 pa0, pa1, pb0, pb1;
    {
        pa0 = va0 ? *(const float4*)(A + (size_t)(row0 + r_a) * K + kq_a * 4)
                  : make_float4(0.f, 0.f, 0.f, 0.f);
        pa1 = va1 ? *(const float4*)(A + (size_t)(row0 + r_a + 64) * K + kq_a * 4)
                  : make_float4(0.f, 0.f, 0.f, 0.f);
        if (tid < 128) {
            pb0 = *(const float4*)(B + (size_t)(2 * p_b) * N + col0 + nq_b * 4);
            pb1 = *(const float4*)(B + (size_t)(2 * p_b + 1) * N + col0 + nq_b * 4);
        }
    }

    for (int kt = 0; kt < KT; kt++) {
        {
            u32 b0, s0, b1, s1;
            split2(pa0.x, pa0.y, b0, s0);
            split2(pa0.z, pa0.w, b1, s1);
            Abig[r_a][2 * kq_a] = b0;  Abig[r_a][2 * kq_a + 1] = b1;
            Asml[r_a][2 * kq_a] = s0;  Asml[r_a][2 * kq_a + 1] = s1;
            split2(pa1.x, pa1.y, b0, s0);
            split2(pa1.z, pa1.w, b1, s1);
            Abig[r_a + 64][2 * kq_a] = b0;  Abig[r_a + 64][2 * kq_a + 1] = b1;
            Asml[r_a + 64][2 * kq_a] = s0;  Asml[r_a + 64][2 * kq_a + 1] = s1;
        }
        if (tid < 128) {
            const float* e0 = &pb0.x;
            const float* e1 = &pb1.x;
#pragma unroll
            for (int j = 0; j < 4; j++) {
                u32 bg, sm;
                split2(e0[j], e1[j], bg, sm);
                Bbig[p_b][4 * nq_b + j] = bg;
                Bsml[p_b][4 * nq_b + j] = sm;
            }
        }
        __syncthreads();

        if (kt + 1 < KT) {
            int k0n = (kt + 1) * 16;
            pa0 = va0 ? *(const float4*)(A + (size_t)(row0 + r_a) * K + k0n + kq_a * 4)
                      : make_float4(0.f, 0.f, 0.f, 0.f);
            pa1 = va1 ? *(const float4*)(A + (size_t)(row0 + r_a + 64) * K + k0n + kq_a * 4)
                      : make_float4(0.f, 0.f, 0.f, 0.f);
            if (tid < 128) {
                pb0 = *(const float4*)(B + (size_t)(k0n + 2 * p_b) * N + col0 + nq_b * 4);
                pb1 = *(const float4*)(B + (size_t)(k0n + 2 * p_b + 1) * N + col0 + nq_b * 4);
            }
        }

        u32 ab[2][4], as[2][4];
#pragma unroll
        for (int mt = 0; mt < 2; mt++) {
            int rb = rw + mt * 16;
            ab[mt][0] = Abig[rb + g][tig];       as[mt][0] = Asml[rb + g][tig];
            ab[mt][1] = Abig[rb + g + 8][tig];   as[mt][1] = Asml[rb + g + 8][tig];
            ab[mt][2] = Abig[rb + g][tig + 4];   as[mt][2] = Asml[rb + g][tig + 4];
            ab[mt][3] = Abig[rb + g + 8][tig + 4]; as[mt][3] = Asml[rb + g + 8][tig + 4];
        }
        u32 bb[4][2], bs[4][2];
#pragma unroll
        for (int nt = 0; nt < 4; nt++) {
            int cb = cw + nt * 8 + g;
            bb[nt][0] = Bbig[tig][cb];      bs[nt][0] = Bsml[tig][cb];
            bb[nt][1] = Bbig[tig + 4][cb];  bs[nt][1] = Bsml[tig + 4][cb];
        }
#pragma unroll
        for (int mt = 0; mt < 2; mt++)
#pragma unroll
            for (int nt = 0; nt < 4; nt++) {
                mma_bf16(acc[mt][nt], ab[mt], bb[nt]);
                mma_bf16(acc[mt][nt], ab[mt], bs[nt]);
                mma_bf16(acc[mt][nt], as[mt], bb[nt]);
            }
        __syncthreads();
    }

#pragma unroll
    for (int nt = 0; nt < 4; nt++) {
        int ccol = col0 + cw + nt * 8 + 2 * tig;
        float2 bbv = *(const float2*)&bias[ccol];
#pragma unroll
        for (int mt = 0; mt < 2; mt++) {
            int r1 = row0 + rw + mt * 16 + g;
            int r2 = r1 + 8;
            float2 o0 = make_float2(acc[mt][nt][0] + bbv.x, acc[mt][nt][1] + bbv.y);
            float2 o1 = make_float2(acc[mt][nt][2] + bbv.x, acc[mt][nt][3] + bbv.y);
            if (r1 < M) {
                *(float2*)(C + (size_t)r1 * N + ccol) = o0;
                if (CFG == 0) *(float2*)((float*)g_h0 + (size_t)r1 * N + ccol) = o0;
            }
            if (r2 < M) {
                *(float2*)(C + (size_t)r2 * N + ccol) = o1;
                if (CFG == 0) *(float2*)((float*)g_h0 + (size_t)r2 * N + ccol) = o1;
            }
        }
    }
}

// ---------------- pooling ----------------
#define STRIP 200
__global__ __launch_bounds__(256) void pool_kernel(
    const float* __restrict__ nr, const int* __restrict__ batch)
{
    int c = threadIdx.x;
    int n0 = blockIdx.x * STRIP;
    int n1 = min(n0 + STRIP, NN);
    if (n0 >= NN) return;
    int curg = clampi(batch[n0], 0, NG - 1);
    float acc = 0.f;
    int cnt_local = 0;
    for (int n = n0; n < n1; n++) {
        int g = clampi(batch[n], 0, NG - 1);
        if (g != curg) {
            atomicAdd(&g_sums[curg * OUTD + c], acc);
            if (c == 0) atomicAdd(&g_cnt[curg], (float)cnt_local);
            acc = 0.f; cnt_local = 0; curg = g;
        }
        acc += nr[(size_t)n * OUTD + c];
        cnt_local++;
    }
    atomicAdd(&g_sums[curg * OUTD + c], acc);
    if (c == 0) atomicAdd(&g_cnt[curg], (float)cnt_local);
}

__global__ void finalize_kernel(float* __restrict__ out) {
    int i = blockIdx.x * blockDim.x + threadIdx.x;
    if (i < NG * OUTD) out[i] = g_sums[i] / fmaxf(g_cnt[i >> 8], 1.0f);
}

// ---------------- launch ----------------
extern "C" void kernel_launch(void* const* d_in, const int* in_sizes, int n_in,
                              void* d_out, int out_size) {
    const float *x = 0, *W_in = 0, *b_in = 0, *alw = 0, *alb = 0,
                *arw = 0, *arb = 0, *W_out = 0, *b_out = 0;
    const int *ei = 0, *batch = 0;
    for (int i = 0; i < n_in; i++) {
        long long s = in_sizes[i];
        const void* p = d_in[i];
        switch (s) {
            case 25600000LL: x     = (const float*)p; break;
            case 1600000LL:  ei    = (const int*)p;   break;
            case 50000LL:    batch = (const int*)p;   break;
            case 131072LL:   W_in  = (const float*)p; break;
            case 65536LL:    W_out = (const float*)p; break;
            case 512LL:      if (!alw) alw = (const float*)p; else arw = (const float*)p; break;
            case 2LL:        if (!alb) alb = (const float*)p; else arb = (const float*)p; break;
            case 256LL:      if (!b_in) b_in = (const float*)p; else b_out = (const float*)p; break;
            default: break;
        }
    }
    float* out = (float*)d_out;

    const int T = 256;
    const int SB = (NN + 1023) / 1024;

    zeroi_kernel<<<(NN + T - 1) / T, T>>>();
    deg_kernel<<<(NE + T - 1) / T, T>>>(ei);
    dinv_kernel<<<(NN + T - 1) / T, T>>>();
    scanA_kernel<<<SB, 1024>>>();
    scanB_kernel<<<1, 64>>>(SB);
    scanC_kernel<<<SB, 1024>>>();
    fill_kernel<<<(NE + T - 1) / T, T>>>(ei);

    dim3 g1((NN + 127) / 128, HIDD / 64);
    bfgemm_kernel<0><<<g1, 256>>>(x, W_in, b_in, nullptr, NN, IND, HIDD);

    attn_kernel<<<(NN + 7) / 8, T>>>(0, alw, alb, arw, arb, 0);
    coef_kernel<<<(NE + T - 1) / T, T>>>(ei);
    gather_kernel<<<(NN + 3) / 4, 256>>>(0, 1);

    attn_kernel<<<(NN + 7) / 8, T>>>(1, alw, alb, arw, arb, 1);
    coef_kernel<<<(NE + T - 1) / T, T>>>(ei);
    gather_kernel<<<(NN + 3) / 4, 256>>>(1, 0);

    dim3 g2((NN + 127) / 128, OUTD / 64);
    bfgemm_kernel<1><<<g2, 256>>>(nullptr, W_out, b_out, out, NN, HIDD, OUTD);

    pool_kernel<<<(NN + STRIP - 1) / STRIP, 256>>>(out, batch);
    finalize_kernel<<<(NG * OUTD + T - 1) / T, T>>>(out + (size_t)NN * OUTD);
}

// round 15
// speedup vs baseline: 1.1301x; 1.1301x over previous
// Round 15: gather unroll REVERTED (regressed 549->622: reg pressure +
// L1tex-queue spread). Instead: coef fused INTO gather via per-warp
// cooperative (src,cf) preload + shfl broadcast -- halves the per-edge
// dependent-load chain and deletes both coef kernels (norm stored CSR-order).
#include <cuda_runtime.h>
#include <stdint.h>

#define NN 50000
#define NE 800000
#define NG 64
#define IND 512
#define HIDD 256
#define OUTD 256
#define EPSV 0.1f

typedef unsigned int u32;

__device__ __forceinline__ int clampi(int v, int lo, int hi) {
    return v < lo ? lo : (v > hi ? hi : v);
}

// ---------------- scratch (device globals) ----------------
__device__ __align__(16) int   g_degi[NN];
__device__ __align__(16) int   g_rowstart[NN];
__device__ __align__(16) int   g_fill[NN];
__device__ __align__(16) int   g_bsum[64];
__device__ __align__(16) int   g_boff[64];
__device__ __align__(16) int   g_csrsrc[NE];
__device__ __align__(16) float g_dinv[NN];
__device__ __align__(16) float g_norm[NE];     // norm in CSR order
__device__ __align__(16) float g_al[NN];
__device__ __align__(16) float g_ar[NN];
__device__ __align__(16) float g_h[(size_t)NN * HIDD];
__device__ __align__(16) float g_h0[(size_t)NN * HIDD];
__device__ __align__(16) float g_agg[(size_t)NN * HIDD];
__device__ __align__(16) float g_sums[NG * OUTD];
__device__ __align__(16) float g_cnt[NG];

// ---------------- setup kernels ----------------
__global__ void zeroi_kernel() {
    int i = blockIdx.x * blockDim.x + threadIdx.x;
    if (i < NN) { g_degi[i] = 0; g_fill[i] = 0; }
    if (i < NG * OUTD) g_sums[i] = 0.f;
    if (i < NG) g_cnt[i] = 0.f;
}

__global__ void deg_kernel(const int* __restrict__ ei) {
    int e = blockIdx.x * blockDim.x + threadIdx.x;
    if (e < NE) {
        int d = clampi(ei[NE + e], 0, NN - 1);
        atomicAdd(&g_degi[d], 1);
    }
}

__global__ void dinv_kernel() {
    int i = blockIdx.x * blockDim.x + threadIdx.x;
    if (i < NN) {
        float d = (float)g_degi[i];
        g_dinv[i] = (d > 0.f) ? rsqrtf(fmaxf(d, 1.f)) : 0.f;
    }
}

// 3-phase scan
__global__ void scanA_kernel() {
    int tid = threadIdx.x;
    int i = blockIdx.x * 1024 + tid;
    int lane = tid & 31, w = tid >> 5;
    int v = (i < NN) ? g_degi[i] : 0;
    int incl = v;
#pragma unroll
    for (int o = 1; o < 32; o <<= 1) {
        int t = __shfl_up_sync(0xFFFFFFFFu, incl, o);
        if (lane >= o) incl += t;
    }
    __shared__ int wsum[32];
    if (lane == 31) wsum[w] = incl;
    __syncthreads();
    if (w == 0) {
        int x = wsum[lane];
        int xi = x;
#pragma unroll
        for (int o = 1; o < 32; o <<= 1) {
            int t = __shfl_up_sync(0xFFFFFFFFu, xi, o);
            if (lane >= o) xi += t;
        }
        wsum[lane] = xi;
    }
    __syncthreads();
    int woff = (w > 0) ? wsum[w - 1] : 0;
    if (i < NN) g_rowstart[i] = woff + incl - v;
    if (tid == 1023) g_bsum[blockIdx.x] = wsum[31];
}

__global__ void scanB_kernel(int nblocks) {
    int tid = threadIdx.x;
    int lane = tid & 31, w = tid >> 5;
    int v = (tid < nblocks) ? g_bsum[tid] : 0;
    int incl = v;
#pragma unroll
    for (int o = 1; o < 32; o <<= 1) {
        int t = __shfl_up_sync(0xFFFFFFFFu, incl, o);
        if (lane >= o) incl += t;
    }
    __shared__ int ws[2];
    if (lane == 31) ws[w] = incl;
    __syncthreads();
    int off = (w == 1) ? ws[0] : 0;
    if (tid < nblocks) g_boff[tid] = off + incl - v;
}

__global__ void scanC_kernel() {
    int i = blockIdx.x * 1024 + threadIdx.x;
    if (i < NN) g_rowstart[i] += g_boff[blockIdx.x];
}

// fill: CSR src + norm stored directly in CSR order (no perm needed)
__global__ void fill_kernel(const int* __restrict__ ei) {
    int e = blockIdx.x * blockDim.x + threadIdx.x;
    if (e < NE) {
        int s = clampi(ei[e], 0, NN - 1);
        int d = clampi(ei[NE + e], 0, NN - 1);
        int pos = g_rowstart[d] + atomicAdd(&g_fill[d], 1);
        pos = clampi(pos, 0, NE - 1);
        g_csrsrc[pos] = s;
        g_norm[pos] = g_dinv[s] * g_dinv[d];
    }
}

// ---------------- per-layer kernels ----------------
__global__ void attn_kernel(int sel,
                            const float* __restrict__ alw, const float* __restrict__ alb,
                            const float* __restrict__ arw, const float* __restrict__ arb,
                            int layer) {
    int node = (blockIdx.x * blockDim.x + threadIdx.x) >> 5;
    int lane = threadIdx.x & 31;
    if (node >= NN) return;
    const float* h = sel ? g_agg : g_h;
    const float* hp = h + (size_t)node * HIDD;
    const float* wl = alw + layer * HIDD;
    const float* wr = arw + layer * HIDD;
    float sl = 0.f, sr = 0.f;
#pragma unroll
    for (int i = 0; i < 8; i++) {
        float v = hp[lane + 32 * i];
        sl = fmaf(v, wl[lane + 32 * i], sl);
        sr = fmaf(v, wr[lane + 32 * i], sr);
    }
#pragma unroll
    for (int o = 16; o; o >>= 1) {
        sl += __shfl_xor_sync(0xFFFFFFFFu, sl, o);
        sr += __shfl_xor_sync(0xFFFFFFFFu, sr, o);
    }
    if (lane == 0) {
        g_al[node] = sl + alb[layer];
        g_ar[node] = sr + arb[layer];
    }
}

// gather with fused coef: per 32-edge chunk each lane preloads (src, norm)
// and computes cf = norm * tanh(al[src] + ar[node]); inner loop broadcasts
// via shfl, so the row-load address never depends on an in-loop load.
__global__ __launch_bounds__(256) void gather_kernel(int sel, int do_relu)
{
    int node = blockIdx.x * 4 + (threadIdx.x >> 6);
    int c = threadIdx.x & 63;       // float4 chunk of the row
    int lane = threadIdx.x & 31;
    if (node >= NN) return;
    const float* h = sel ? g_agg : g_h;
    float* outp    = sel ? g_h   : g_agg;
    int beg = g_rowstart[node];
    int n = g_degi[node];
    float ar_d = g_ar[node];

    float4 acc = ((const float4*)(g_h0 + (size_t)node * HIDD))[c];
    acc.x *= EPSV; acc.y *= EPSV; acc.z *= EPSV; acc.w *= EPSV;

    for (int base = 0; base < n; base += 32) {
        int cnt = min(32, n - base);
        int s_l = 0; float cf_l = 0.f;
        if (lane < cnt) {
            s_l = __ldg(&g_csrsrc[beg + base + lane]);
            float nrm = __ldg(&g_norm[beg + base + lane]);
            cf_l = nrm * tanhf(__ldg(&g_al[s_l]) + ar_d);
        }
        for (int j = 0; j < cnt; j++) {
            int s   = __shfl_sync(0xFFFFFFFFu, s_l, j);
            float cf = __shfl_sync(0xFFFFFFFFu, cf_l, j);
            float4 v = __ldg((const float4*)(h + (size_t)s * HIDD) + c);
            acc.x = fmaf(cf, v.x, acc.x);
            acc.y = fmaf(cf, v.y, acc.y);
            acc.z = fmaf(cf, v.z, acc.z);
            acc.w = fmaf(cf, v.w, acc.w);
        }
    }
    if (do_relu) {
        acc.x = fmaxf(acc.x, 0.f); acc.y = fmaxf(acc.y, 0.f);
        acc.z = fmaxf(acc.z, 0.f); acc.w = fmaxf(acc.w, 0.f);
    }
    ((float4*)(outp + (size_t)node * HIDD))[c] = acc;
}

// ---------------- bf16 3-term tensor-core GEMM ----------------
__device__ __forceinline__ u32 cvt_bf2(float lo, float hi) {
    u32 d;
    asm("cvt.rn.bf16x2.f32 %0, %1, %2;" : "=r"(d) : "f"(hi), "f"(lo));
    return d;
}
__device__ __forceinline__ void split2(float lo, float hi, u32& big, u32& sml) {
    big = cvt_bf2(lo, hi);
    float blo = __uint_as_float(big << 16);
    float bhi = __uint_as_float(big & 0xFFFF0000u);
    sml = cvt_bf2(lo - blo, hi - bhi);
}
__device__ __forceinline__ void mma_bf16(float* c, const u32* a, const u32* b) {
    asm volatile(
        "mma.sync.aligned.m16n8k16.row.col.f32.bf16.bf16.f32 "
        "{%0,%1,%2,%3}, {%4,%5,%6,%7}, {%8,%9}, {%0,%1,%2,%3};"
        : "+f"(c[0]), "+f"(c[1]), "+f"(c[2]), "+f"(c[3])
        : "r"(a[0]), "r"(a[1]), "r"(a[2]), "r"(a[3]), "r"(b[0]), "r"(b[1]));
}

template <int CFG>
__global__ __launch_bounds__(256) void bfgemm_kernel(
    const float* __restrict__ Aext, const float* __restrict__ B,
    const float* __restrict__ bias, float* __restrict__ Cext,
    int M, int K, int N)
{
    const float* A = (CFG == 0) ? Aext : (const float*)g_h;
    float* C       = (CFG == 0) ? (float*)g_h : Cext;

    __shared__ u32 Abig[128][20], Asml[128][20];
    __shared__ u32 Bbig[8][72],  Bsml[8][72];

    const int tid  = threadIdx.x;
    const int lane = tid & 31;
    const int warp = tid >> 5;
    const int wm = warp >> 1;
    const int wn = warp & 1;
    const int g   = lane >> 2;
    const int tig = lane & 3;
    const int row0 = blockIdx.x * 128;
    const int col0 = blockIdx.y * 64;
    const int rw = wm * 32;
    const int cw = wn * 32;

    float acc[2][4][4];
#pragma unroll
    for (int mt = 0; mt < 2; mt++)
#pragma unroll
        for (int nt = 0; nt < 4; nt++)
#pragma unroll
            for (int r = 0; r < 4; r++) acc[mt][nt][r] = 0.f;

    const int r_a  = tid >> 2;
    const int kq_a = tid & 3;
    const bool va0 = (row0 + r_a) < M;
    const bool va1 = (row0 + r_a + 64) < M;
    const int p_b  = tid >> 4;
    const int nq_b = tid & 15;

    const int KT = K >> 4;
    float4 pa0, pa1, pb0, pb1;
    {
        pa0 = va0 ? *(const float4*)(A + (size_t)(row0 + r_a) * K + kq_a * 4)
                  : make_float4(0.f, 0.f, 0.f, 0.f);
        pa1 = va1 ? *(const float4*)(A + (size_t)(row0 + r_a + 64) * K + kq_a * 4)
                  : make_float4(0.f, 0.f, 0.f, 0.f);
        if (tid < 128) {
            pb0 = *(const float4*)(B + (size_t)(2 * p_b) * N + col0 + nq_b * 4);
            pb1 = *(const float4*)(B + (size_t)(2 * p_b + 1) * N + col0 + nq_b * 4);
        }
    }

    for (int kt = 0; kt < KT; kt++) {
        {
            u32 b0, s0, b1, s1;
            split2(pa0.x, pa0.y, b0, s0);
            split2(pa0.z, pa0.w, b1, s1);
            Abig[r_a][2 * kq_a] = b0;  Abig[r_a][2 * kq_a + 1] = b1;
            Asml[r_a][2 * kq_a] = s0;  Asml[r_a][2 * kq_a + 1] = s1;
            split2(pa1.x, pa1.y, b0, s0);
            split2(pa1.z, pa1.w, b1, s1);
            Abig[r_a + 64][2 * kq_a] = b0;  Abig[r_a + 64][2 * kq_a + 1] = b1;
            Asml[r_a + 64][2 * kq_a] = s0;  Asml[r_a + 64][2 * kq_a + 1] = s1;
        }
        if (tid < 128) {
            const float* e0 = &pb0.x;
            const float* e1 = &pb1.x;
#pragma unroll
            for (int j = 0; j < 4; j++) {
                u32 bg, sm;
                split2(e0[j], e1[j], bg, sm);
                Bbig[p_b][4 * nq_b + j] = bg;
                Bsml[p_b][4 * nq_b + j] = sm;
            }
        }
        __syncthreads();

        if (kt + 1 < KT) {
            int k0n = (kt + 1) * 16;
            pa0 = va0 ? *(const float4*)(A + (size_t)(row0 + r_a) * K + k0n + kq_a * 4)
                      : make_float4(0.f, 0.f, 0.f, 0.f);
            pa1 = va1 ? *(const float4*)(A + (size_t)(row0 + r_a + 64) * K + k0n + kq_a * 4)
                      : make_float4(0.f, 0.f, 0.f, 0.f);
            if (tid < 128) {
                pb0 = *(const float4*)(B + (size_t)(k0n + 2 * p_b) * N + col0 + nq_b * 4);
                pb1 = *(const float4*)(B + (size_t)(k0n + 2 * p_b + 1) * N + col0 + nq_b * 4);
            }
        }

        u32 ab[2][4], as[2][4];
#pragma unroll
        for (int mt = 0; mt < 2; mt++) {
            int rb = rw + mt * 16;
            ab[mt][0] = Abig[rb + g][tig];       as[mt][0] = Asml[rb + g][tig];
            ab[mt][1] = Abig[rb + g + 8][tig];   as[mt][1] = Asml[rb + g + 8][tig];
            ab[mt][2] = Abig[rb + g][tig + 4];   as[mt][2] = Asml[rb + g][tig + 4];
            ab[mt][3] = Abig[rb + g + 8][tig + 4]; as[mt][3] = Asml[rb + g + 8][tig + 4];
        }
        u32 bb[4][2], bs[4][2];
#pragma unroll
        for (int nt = 0; nt < 4; nt++) {
            int cb = cw + nt * 8 + g;
            bb[nt][0] = Bbig[tig][cb];      bs[nt][0] = Bsml[tig][cb];
            bb[nt][1] = Bbig[tig + 4][cb];  bs[nt][1] = Bsml[tig + 4][cb];
        }
#pragma unroll
        for (int mt = 0; mt < 2; mt++)
#pragma unroll
            for (int nt = 0; nt < 4; nt++) {
                mma_bf16(acc[mt][nt], ab[mt], bb[nt]);
                mma_bf16(acc[mt][nt], ab[mt], bs[nt]);
                mma_bf16(acc[mt][nt], as[mt], bb[nt]);
            }
        __syncthreads();
    }

#pragma unroll
    for (int nt = 0; nt < 4; nt++) {
        int ccol = col0 + cw + nt * 8 + 2 * tig;
        float2 bbv = *(const float2*)&bias[ccol];
#pragma unroll
        for (int mt = 0; mt < 2; mt++) {
            int r1 = row0 + rw + mt * 16 + g;
            int r2 = r1 + 8;
            float2 o0 = make_float2(acc[mt][nt][0] + bbv.x, acc[mt][nt][1] + bbv.y);
            float2 o1 = make_float2(acc[mt][nt][2] + bbv.x, acc[mt][nt][3] + bbv.y);
            if (r1 < M) {
                *(float2*)(C + (size_t)r1 * N + ccol) = o0;
                if (CFG == 0) *(float2*)((float*)g_h0 + (size_t)r1 * N + ccol) = o0;
            }
            if (r2 < M) {
                *(float2*)(C + (size_t)r2 * N + ccol) = o1;
                if (CFG == 0) *(float2*)((float*)g_h0 + (size_t)r2 * N + ccol) = o1;
            }
        }
    }
}

// ---------------- pooling ----------------
#define STRIP 200
__global__ __launch_bounds__(256) void pool_kernel(
    const float* __restrict__ nr, const int* __restrict__ batch)
{
    int c = threadIdx.x;
    int n0 = blockIdx.x * STRIP;
    int n1 = min(n0 + STRIP, NN);
    if (n0 >= NN) return;
    int curg = clampi(batch[n0], 0, NG - 1);
    float acc = 0.f;
    int cnt_local = 0;
    for (int n = n0; n < n1; n++) {
        int g = clampi(batch[n], 0, NG - 1);
        if (g != curg) {
            atomicAdd(&g_sums[curg * OUTD + c], acc);
            if (c == 0) atomicAdd(&g_cnt[curg], (float)cnt_local);
            acc = 0.f; cnt_local = 0; curg = g;
        }
        acc += nr[(size_t)n * OUTD + c];
        cnt_local++;
    }
    atomicAdd(&g_sums[curg * OUTD + c], acc);
    if (c == 0) atomicAdd(&g_cnt[curg], (float)cnt_local);
}

__global__ void finalize_kernel(float* __restrict__ out) {
    int i = blockIdx.x * blockDim.x + threadIdx.x;
    if (i < NG * OUTD) out[i] = g_sums[i] / fmaxf(g_cnt[i >> 8], 1.0f);
}

// ---------------- launch ----------------
extern "C" void kernel_launch(void* const* d_in, const int* in_sizes, int n_in,
                              void* d_out, int out_size) {
    const float *x = 0, *W_in = 0, *b_in = 0, *alw = 0, *alb = 0,
                *arw = 0, *arb = 0, *W_out = 0, *b_out = 0;
    const int *ei = 0, *batch = 0;
    for (int i = 0; i < n_in; i++) {
        long long s = in_sizes[i];
        const void* p = d_in[i];
        switch (s) {
            case 25600000LL: x     = (const float*)p; break;
            case 1600000LL:  ei    = (const int*)p;   break;
            case 50000LL:    batch = (const int*)p;   break;
            case 131072LL:   W_in  = (const float*)p; break;
            case 65536LL:    W_out = (const float*)p; break;
            case 512LL:      if (!alw) alw = (const float*)p; else arw = (const float*)p; break;
            case 2LL:        if (!alb) alb = (const float*)p; else arb = (const float*)p; break;
            case 256LL:      if (!b_in) b_in = (const float*)p; else b_out = (const float*)p; break;
            default: break;
        }
    }
    float* out = (float*)d_out;

    const int T = 256;
    const int SB = (NN + 1023) / 1024;

    zeroi_kernel<<<(NN + T - 1) / T, T>>>();
    deg_kernel<<<(NE + T - 1) / T, T>>>(ei);
    dinv_kernel<<<(NN + T - 1) / T, T>>>();
    scanA_kernel<<<SB, 1024>>>();
    scanB_kernel<<<1, 64>>>(SB);
    scanC_kernel<<<SB, 1024>>>();
    fill_kernel<<<(NE + T - 1) / T, T>>>(ei);

    dim3 g1((NN + 127) / 128, HIDD / 64);
    bfgemm_kernel<0><<<g1, 256>>>(x, W_in, b_in, nullptr, NN, IND, HIDD);

    // layer 0 (coef fused into gather)
    attn_kernel<<<(NN + 7) / 8, T>>>(0, alw, alb, arw, arb, 0);
    gather_kernel<<<(NN + 3) / 4, 256>>>(0, 1);

    // layer 1
    attn_kernel<<<(NN + 7) / 8, T>>>(1, alw, alb, arw, arb, 1);
    gather_kernel<<<(NN + 3) / 4, 256>>>(1, 0);

    dim3 g2((NN + 127) / 128, OUTD / 64);
    bfgemm_kernel<1><<<g2, 256>>>(nullptr, W_out, b_out, out, NN, HIDD, OUTD);

    pool_kernel<<<(NN + STRIP - 1) / STRIP, 256>>>(out, batch);
    finalize_kernel<<<(NG * OUTD + T - 1) / T, T>>>(out + (size_t)NN * OUTD);
}

// round 16
// speedup vs baseline: 1.1385x; 1.0074x over previous
// Round 16: fp16 gather-source rows. GEMM1 epilogue emits an fp16 copy of h;
// gathers read fp16 (half the L2 bytes), accumulate fp32; attn reads fp16
// vectorized. EPS*h0 term and all outputs consumed by GEMMs stay fp32.
#include <cuda_runtime.h>
#include <cuda_fp16.h>
#include <stdint.h>

#define NN 50000
#define NE 800000
#define NG 64
#define IND 512
#define HIDD 256
#define OUTD 256
#define EPSV 0.1f

typedef unsigned int u32;

__device__ __forceinline__ int clampi(int v, int lo, int hi) {
    return v < lo ? lo : (v > hi ? hi : v);
}

// ---------------- scratch (device globals) ----------------
__device__ __align__(16) int    g_degi[NN];
__device__ __align__(16) int    g_rowstart[NN];
__device__ __align__(16) int    g_fill[NN];
__device__ __align__(16) int    g_bsum[64];
__device__ __align__(16) int    g_boff[64];
__device__ __align__(16) int    g_csrsrc[NE];
__device__ __align__(16) float  g_dinv[NN];
__device__ __align__(16) float  g_norm[NE];    // norm in CSR order
__device__ __align__(16) float  g_al[NN];
__device__ __align__(16) float  g_ar[NN];
__device__ __align__(16) float  g_h[(size_t)NN * HIDD];
__device__ __align__(16) float  g_h0[(size_t)NN * HIDD];
__device__ __align__(16) float  g_agg[(size_t)NN * HIDD];
__device__ __align__(16) __half g_hx[(size_t)NN * HIDD];    // fp16 copy of h
__device__ __align__(16) __half g_aggx[(size_t)NN * HIDD];  // fp16 copy of agg
__device__ __align__(16) float  g_sums[NG * OUTD];
__device__ __align__(16) float  g_cnt[NG];

// ---------------- setup kernels ----------------
__global__ void zeroi_kernel() {
    int i = blockIdx.x * blockDim.x + threadIdx.x;
    if (i < NN) { g_degi[i] = 0; g_fill[i] = 0; }
    if (i < NG * OUTD) g_sums[i] = 0.f;
    if (i < NG) g_cnt[i] = 0.f;
}

__global__ void deg_kernel(const int* __restrict__ ei) {
    int e = blockIdx.x * blockDim.x + threadIdx.x;
    if (e < NE) {
        int d = clampi(ei[NE + e], 0, NN - 1);
        atomicAdd(&g_degi[d], 1);
    }
}

__global__ void dinv_kernel() {
    int i = blockIdx.x * blockDim.x + threadIdx.x;
    if (i < NN) {
        float d = (float)g_degi[i];
        g_dinv[i] = (d > 0.f) ? rsqrtf(fmaxf(d, 1.f)) : 0.f;
    }
}

// 3-phase scan
__global__ void scanA_kernel() {
    int tid = threadIdx.x;
    int i = blockIdx.x * 1024 + tid;
    int lane = tid & 31, w = tid >> 5;
    int v = (i < NN) ? g_degi[i] : 0;
    int incl = v;
#pragma unroll
    for (int o = 1; o < 32; o <<= 1) {
        int t = __shfl_up_sync(0xFFFFFFFFu, incl, o);
        if (lane >= o) incl += t;
    }
    __shared__ int wsum[32];
    if (lane == 31) wsum[w] = incl;
    __syncthreads();
    if (w == 0) {
        int x = wsum[lane];
        int xi = x;
#pragma unroll
        for (int o = 1; o < 32; o <<= 1) {
            int t = __shfl_up_sync(0xFFFFFFFFu, xi, o);
            if (lane >= o) xi += t;
        }
        wsum[lane] = xi;
    }
    __syncthreads();
    int woff = (w > 0) ? wsum[w - 1] : 0;
    if (i < NN) g_rowstart[i] = woff + incl - v;
    if (tid == 1023) g_bsum[blockIdx.x] = wsum[31];
}

__global__ void scanB_kernel(int nblocks) {
    int tid = threadIdx.x;
    int lane = tid & 31, w = tid >> 5;
    int v = (tid < nblocks) ? g_bsum[tid] : 0;
    int incl = v;
#pragma unroll
    for (int o = 1; o < 32; o <<= 1) {
        int t = __shfl_up_sync(0xFFFFFFFFu, incl, o);
        if (lane >= o) incl += t;
    }
    __shared__ int ws[2];
    if (lane == 31) ws[w] = incl;
    __syncthreads();
    int off = (w == 1) ? ws[0] : 0;
    if (tid < nblocks) g_boff[tid] = off + incl - v;
}

__global__ void scanC_kernel() {
    int i = blockIdx.x * 1024 + threadIdx.x;
    if (i < NN) g_rowstart[i] += g_boff[blockIdx.x];
}

__global__ void fill_kernel(const int* __restrict__ ei) {
    int e = blockIdx.x * blockDim.x + threadIdx.x;
    if (e < NE) {
        int s = clampi(ei[e], 0, NN - 1);
        int d = clampi(ei[NE + e], 0, NN - 1);
        int pos = g_rowstart[d] + atomicAdd(&g_fill[d], 1);
        pos = clampi(pos, 0, NE - 1);
        g_csrsrc[pos] = s;
        g_norm[pos] = g_dinv[s] * g_dinv[d];
    }
}

// ---------------- per-layer kernels ----------------
// attn over fp16 rows: lane handles 8 contiguous halves (one uint4 load).
__global__ void attn_kernel(int sel,
                            const float* __restrict__ alw, const float* __restrict__ alb,
                            const float* __restrict__ arw, const float* __restrict__ arb,
                            int layer) {
    int node = (blockIdx.x * blockDim.x + threadIdx.x) >> 5;
    int lane = threadIdx.x & 31;
    if (node >= NN) return;
    const __half* hx = sel ? g_aggx : g_hx;
    const __half* hp = hx + (size_t)node * HIDD;
    const float* wl = alw + layer * HIDD;
    const float* wr = arw + layer * HIDD;
    int base = lane * 8;
    uint4 raw = __ldg((const uint4*)(hp + base));
    const __half2* hh = (const __half2*)&raw;
    float4 wl0 = __ldg((const float4*)(wl + base));
    float4 wl1 = __ldg((const float4*)(wl + base + 4));
    float4 wr0 = __ldg((const float4*)(wr + base));
    float4 wr1 = __ldg((const float4*)(wr + base + 4));
    float v[8];
    float2 p;
    p = __half22float2(hh[0]); v[0] = p.x; v[1] = p.y;
    p = __half22float2(hh[1]); v[2] = p.x; v[3] = p.y;
    p = __half22float2(hh[2]); v[4] = p.x; v[5] = p.y;
    p = __half22float2(hh[3]); v[6] = p.x; v[7] = p.y;
    float sl = v[0]*wl0.x + v[1]*wl0.y + v[2]*wl0.z + v[3]*wl0.w
             + v[4]*wl1.x + v[5]*wl1.y + v[6]*wl1.z + v[7]*wl1.w;
    float sr = v[0]*wr0.x + v[1]*wr0.y + v[2]*wr0.z + v[3]*wr0.w
             + v[4]*wr1.x + v[5]*wr1.y + v[6]*wr1.z + v[7]*wr1.w;
#pragma unroll
    for (int o = 16; o; o >>= 1) {
        sl += __shfl_xor_sync(0xFFFFFFFFu, sl, o);
        sr += __shfl_xor_sync(0xFFFFFFFFu, sr, o);
    }
    if (lane == 0) {
        g_al[node] = sl + alb[layer];
        g_ar[node] = sr + arb[layer];
    }
}

// gather, fused coef, fp16 source rows. sel==0: src g_hx, dst g_agg+g_aggx.
// sel==1: src g_aggx, dst g_h (fp32 only).
__global__ __launch_bounds__(256) void gather_kernel(int sel, int do_relu)
{
    int node = blockIdx.x * 4 + (threadIdx.x >> 6);
    int c = threadIdx.x & 63;       // 4-element chunk of the row
    int lane = threadIdx.x & 31;
    if (node >= NN) return;
    const __half* hx = sel ? g_aggx : g_hx;
    float* outp      = sel ? g_h    : g_agg;
    int beg = g_rowstart[node];
    int n = g_degi[node];
    float ar_d = g_ar[node];

    float4 acc = ((const float4*)(g_h0 + (size_t)node * HIDD))[c];
    acc.x *= EPSV; acc.y *= EPSV; acc.z *= EPSV; acc.w *= EPSV;

    for (int base = 0; base < n; base += 32) {
        int cnt = min(32, n - base);
        int s_l = 0; float cf_l = 0.f;
        if (lane < cnt) {
            s_l = __ldg(&g_csrsrc[beg + base + lane]);
            float nrm = __ldg(&g_norm[beg + base + lane]);
            cf_l = nrm * tanhf(__ldg(&g_al[s_l]) + ar_d);
        }
        for (int j = 0; j < cnt; j++) {
            int s    = __shfl_sync(0xFFFFFFFFu, s_l, j);
            float cf = __shfl_sync(0xFFFFFFFFu, cf_l, j);
            uint2 raw = __ldg((const uint2*)(hx + (size_t)s * HIDD) + c);
            float2 f01 = __half22float2(*(const __half2*)&raw.x);
            float2 f23 = __half22float2(*(const __half2*)&raw.y);
            acc.x = fmaf(cf, f01.x, acc.x);
            acc.y = fmaf(cf, f01.y, acc.y);
            acc.z = fmaf(cf, f23.x, acc.z);
            acc.w = fmaf(cf, f23.y, acc.w);
        }
    }
    if (do_relu) {
        acc.x = fmaxf(acc.x, 0.f); acc.y = fmaxf(acc.y, 0.f);
        acc.z = fmaxf(acc.z, 0.f); acc.w = fmaxf(acc.w, 0.f);
    }
    ((float4*)(outp + (size_t)node * HIDD))[c] = acc;
    if (sel == 0) {   // emit fp16 copy for next layer's gather/attn
        uint2 packed;
        *(__half2*)&packed.x = __floats2half2_rn(acc.x, acc.y);
        *(__half2*)&packed.y = __floats2half2_rn(acc.z, acc.w);
        ((uint2*)(g_aggx + (size_t)node * HIDD))[c] = packed;
    }
}

// ---------------- bf16 3-term tensor-core GEMM ----------------
__device__ __forceinline__ u32 cvt_bf2(float lo, float hi) {
    u32 d;
    asm("cvt.rn.bf16x2.f32 %0, %1, %2;" : "=r"(d) : "f"(hi), "f"(lo));
    return d;
}
__device__ __forceinline__ void split2(float lo, float hi, u32& big, u32& sml) {
    big = cvt_bf2(lo, hi);
    float blo = __uint_as_float(big << 16);
    float bhi = __uint_as_float(big & 0xFFFF0000u);
    sml = cvt_bf2(lo - blo, hi - bhi);
}
__device__ __forceinline__ void mma_bf16(float* c, const u32* a, const u32* b) {
    asm volatile(
        "mma.sync.aligned.m16n8k16.row.col.f32.bf16.bf16.f32 "
        "{%0,%1,%2,%3}, {%4,%5,%6,%7}, {%8,%9}, {%0,%1,%2,%3};"
        : "+f"(c[0]), "+f"(c[1]), "+f"(c[2]), "+f"(c[3])
        : "r"(a[0]), "r"(a[1]), "r"(a[2]), "r"(a[3]), "r"(b[0]), "r"(b[1]));
}

// CFG==0: A=Aext(x), C=g_h + g_h0 + g_hx(fp16). CFG==1: A=g_h, C=Cext.
template <int CFG>
__global__ __launch_bounds__(256) void bfgemm_kernel(
    const float* __restrict__ Aext, const float* __restrict__ B,
    const float* __restrict__ bias, float* __restrict__ Cext,
    int M, int K, int N)
{
    const float* A = (CFG == 0) ? Aext : (const float*)g_h;
    float* C       = (CFG == 0) ? (float*)g_h : Cext;

    __shared__ u32 Abig[128][20], Asml[128][20];
    __shared__ u32 Bbig[8][72],  Bsml[8][72];

    const int tid  = threadIdx.x;
    const int lane = tid & 31;
    const int warp = tid >> 5;
    const int wm = warp >> 1;
    const int wn = warp & 1;
    const int g   = lane >> 2;
    const int tig = lane & 3;
    const int row0 = blockIdx.x * 128;
    const int col0 = blockIdx.y * 64;
    const int rw = wm * 32;
    const int cw = wn * 32;

    float acc[2][4][4];
#pragma unroll
    for (int mt = 0; mt < 2; mt++)
#pragma unroll
        for (int nt = 0; nt < 4; nt++)
#pragma unroll
            for (int r = 0; r < 4; r++) acc[mt][nt][r] = 0.f;

    const int r_a  = tid >> 2;
    const int kq_a = tid & 3;
    const bool va0 = (row0 + r_a) < M;
    const bool va1 = (row0 + r_a + 64) < M;
    const int p_b  = tid >> 4;
    const int nq_b = tid & 15;

    const int KT = K >> 4;
    float4 pa0, pa1, pb0, pb1;
    {
        pa0 = va0 ? *(const float4*)(A + (size_t)(row0 + r_a) * K + kq_a * 4)
                  : make_float4(0.f, 0.f, 0.f, 0.f);
        pa1 = va1 ? *(const float4*)(A + (size_t)(row0 + r_a + 64) * K + kq_a * 4)
                  : make_float4(0.f, 0.f, 0.f, 0.f);
        if (tid < 128) {
            pb0 = *(const float4*)(B + (size_t)(2 * p_b) * N + col0 + nq_b * 4);
            pb1 = *(const float4*)(B + (size_t)(2 * p_b + 1) * N + col0 + nq_b * 4);
        }
    }

    for (int kt = 0; kt < KT; kt++) {
        {
            u32 b0, s0, b1, s1;
            split2(pa0.x, pa0.y, b0, s0);
            split2(pa0.z, pa0.w, b1, s1);
            Abig[r_a][2 * kq_a] = b0;  Abig[r_a][2 * kq_a + 1] = b1;
            Asml[r_a][2 * kq_a] = s0;  Asml[r_a][2 * kq_a + 1] = s1;
            split2(pa1.x, pa1.y, b0, s0);
            split2(pa1.z, pa1.w, b1, s1);
            Abig[r_a + 64][2 * kq_a] = b0;  Abig[r_a + 64][2 * kq_a + 1] = b1;
            Asml[r_a + 64][2 * kq_a] = s0;  Asml[r_a + 64][2 * kq_a + 1] = s1;
        }
        if (tid < 128) {
            const float* e0 = &pb0.x;
            const float* e1 = &pb1.x;
#pragma unroll
            for (int j = 0; j < 4; j++) {
                u32 bg, sm;
                split2(e0[j], e1[j], bg, sm);
                Bbig[p_b][4 * nq_b + j] = bg;
                Bsml[p_b][4 * nq_b + j] = sm;
            }
        }
        __syncthreads();

        if (kt + 1 < KT) {
            int k0n = (kt + 1) * 16;
            pa0 = va0 ? *(const float4*)(A + (size_t)(row0 + r_a) * K + k0n + kq_a * 4)
                      : make_float4(0.f, 0.f, 0.f, 0.f);
            pa1 = va1 ? *(const float4*)(A + (size_t)(row0 + r_a + 64) * K + k0n + kq_a * 4)
                      : make_float4(0.f, 0.f, 0.f, 0.f);
            if (tid < 128) {
                pb0 = *(const float4*)(B + (size_t)(k0n + 2 * p_b) * N + col0 + nq_b * 4);
                pb1 = *(const float4*)(B + (size_t)(k0n + 2 * p_b + 1) * N + col0 + nq_b * 4);
            }
        }

        u32 ab[2][4], as[2][4];
#pragma unroll
        for (int mt = 0; mt < 2; mt++) {
            int rb = rw + mt * 16;
            ab[mt][0] = Abig[rb + g][tig];       as[mt][0] = Asml[rb + g][tig];
            ab[mt][1] = Abig[rb + g + 8][tig];   as[mt][1] = Asml[rb + g + 8][tig];
            ab[mt][2] = Abig[rb + g][tig + 4];   as[mt][2] = Asml[rb + g][tig + 4];
            ab[mt][3] = Abig[rb + g + 8][tig + 4]; as[mt][3] = Asml[rb + g + 8][tig + 4];
        }
        u32 bb[4][2], bs[4][2];
#pragma unroll
        for (int nt = 0; nt < 4; nt++) {
            int cb = cw + nt * 8 + g;
            bb[nt][0] = Bbig[tig][cb];      bs[nt][0] = Bsml[tig][cb];
            bb[nt][1] = Bbig[tig + 4][cb];  bs[nt][1] = Bsml[tig + 4][cb];
        }
#pragma unroll
        for (int mt = 0; mt < 2; mt++)
#pragma unroll
            for (int nt = 0; nt < 4; nt++) {
                mma_bf16(acc[mt][nt], ab[mt], bb[nt]);
                mma_bf16(acc[mt][nt], ab[mt], bs[nt]);
                mma_bf16(acc[mt][nt], as[mt], bb[nt]);
            }
        __syncthreads();
    }

#pragma unroll
    for (int nt = 0; nt < 4; nt++) {
        int ccol = col0 + cw + nt * 8 + 2 * tig;
        float2 bbv = *(const float2*)&bias[ccol];
#pragma unroll
        for (int mt = 0; mt < 2; mt++) {
            int r1 = row0 + rw + mt * 16 + g;
            int r2 = r1 + 8;
            float2 o0 = make_float2(acc[mt][nt][0] + bbv.x, acc[mt][nt][1] + bbv.y);
            float2 o1 = make_float2(acc[mt][nt][2] + bbv.x, acc[mt][nt][3] + bbv.y);
            if (r1 < M) {
                *(float2*)(C + (size_t)r1 * N + ccol) = o0;
                if (CFG == 0) {
                    *(float2*)((float*)g_h0 + (size_t)r1 * N + ccol) = o0;
                    *(__half2*)(g_hx + (size_t)r1 * N + ccol) = __floats2half2_rn(o0.x, o0.y);
                }
            }
            if (r2 < M) {
                *(float2*)(C + (size_t)r2 * N + ccol) = o1;
                if (CFG == 0) {
                    *(float2*)((float*)g_h0 + (size_t)r2 * N + ccol) = o1;
                    *(__half2*)(g_hx + (size_t)r2 * N + ccol) = __floats2half2_rn(o1.x, o1.y);
                }
            }
        }
    }
}

// ---------------- pooling ----------------
#define STRIP 200
__global__ __launch_bounds__(256) void pool_kernel(
    const float* __restrict__ nr, const int* __restrict__ batch)
{
    int c = threadIdx.x;
    int n0 = blockIdx.x * STRIP;
    int n1 = min(n0 + STRIP, NN);
    if (n0 >= NN) return;
    int curg = clampi(batch[n0], 0, NG - 1);
    float acc = 0.f;
    int cnt_local = 0;
    for (int n = n0; n < n1; n++) {
        int g = clampi(batch[n], 0, NG - 1);
        if (g != curg) {
            atomicAdd(&g_sums[curg * OUTD + c], acc);
            if (c == 0) atomicAdd(&g_cnt[curg], (float)cnt_local);
            acc = 0.f; cnt_local = 0; curg = g;
        }
        acc += nr[(size_t)n * OUTD + c];
        cnt_local++;
    }
    atomicAdd(&g_sums[curg * OUTD + c], acc);
    if (c == 0) atomicAdd(&g_cnt[curg], (float)cnt_local);
}

__global__ void finalize_kernel(float* __restrict__ out) {
    int i = blockIdx.x * blockDim.x + threadIdx.x;
    if (i < NG * OUTD) out[i] = g_sums[i] / fmaxf(g_cnt[i >> 8], 1.0f);
}

// ---------------- launch ----------------
extern "C" void kernel_launch(void* const* d_in, const int* in_sizes, int n_in,
                              void* d_out, int out_size) {
    const float *x = 0, *W_in = 0, *b_in = 0, *alw = 0, *alb = 0,
                *arw = 0, *arb = 0, *W_out = 0, *b_out = 0;
    const int *ei = 0, *batch = 0;
    for (int i = 0; i < n_in; i++) {
        long long s = in_sizes[i];
        const void* p = d_in[i];
        switch (s) {
            case 25600000LL: x     = (const float*)p; break;
            case 1600000LL:  ei    = (const int*)p;   break;
            case 50000LL:    batch = (const int*)p;   break;
            case 131072LL:   W_in  = (const float*)p; break;
            case 65536LL:    W_out = (const float*)p; break;
            case 512LL:      if (!alw) alw = (const float*)p; else arw = (const float*)p; break;
            case 2LL:        if (!alb) alb = (const float*)p; else arb = (const float*)p; break;
            case 256LL:      if (!b_in) b_in = (const float*)p; else b_out = (const float*)p; break;
            default: break;
        }
    }
    float* out = (float*)d_out;

    const int T = 256;
    const int SB = (NN + 1023) / 1024;

    zeroi_kernel<<<(NN + T - 1) / T, T>>>();
    deg_kernel<<<(NE + T - 1) / T, T>>>(ei);
    dinv_kernel<<<(NN + T - 1) / T, T>>>();
    scanA_kernel<<<SB, 1024>>>();
    scanB_kernel<<<1, 64>>>(SB);
    scanC_kernel<<<SB, 1024>>>();
    fill_kernel<<<(NE + T - 1) / T, T>>>(ei);

    dim3 g1((NN + 127) / 128, HIDD / 64);
    bfgemm_kernel<0><<<g1, 256>>>(x, W_in, b_in, nullptr, NN, IND, HIDD);

    // layer 0 (coef fused into gather, fp16 source)
    attn_kernel<<<(NN + 7) / 8, T>>>(0, alw, alb, arw, arb, 0);
    gather_kernel<<<(NN + 3) / 4, 256>>>(0, 1);

    // layer 1
    attn_kernel<<<(NN + 7) / 8, T>>>(1, alw, alb, arw, arb, 1);
    gather_kernel<<<(NN + 3) / 4, 256>>>(1, 0);

    dim3 g2((NN + 127) / 128, OUTD / 64);
    bfgemm_kernel<1><<<g2, 256>>>(nullptr, W_out, b_out, out, NN, HIDD, OUTD);

    pool_kernel<<<(NN + STRIP - 1) / STRIP, 256>>>(out, batch);
    finalize_kernel<<<(NG * OUTD + T - 1) / T, T>>>(out + (size_t)NN * OUTD);
}